// round 9
// baseline (speedup 1.0000x reference)
#include <cuda_runtime.h>
#include <cstdint>

// Neo-Hookean 3D material point: psi, Cauchy (Voigt 6), DDSDDE (6x6) per point.
// Output layout (flattened tuple): [N] psi | [N,6] Cauchy6 | [N,36] DDSDDE.
//
// R8: warp-local PERSISTENT pipeline. Each warp grid-strides over 32-point
// tiles with (a) cp.async.cg prefetch of the NEXT tile's F overlapping this
// tile's compute, and (b) the dd bulk-TMA drain of tile t retired only at
// tile t+1 (deferred wait). No __syncthreads anywhere. This amortizes the
// cold-LDG latency and the TMA completion tail once per warp instead of
// once per 256-pt block (R4-R7 plateaued at ~32us with both pipes <60%:
// latency-chain bound, not throughput bound).

#define TPB 256
#define ROW 36
#define WARPS_PER_BLOCK 8
#define WARP_F_FLOATS  (32 * 9)             // 1152 B per warp
#define WARP_DD_FLOATS (32 * ROW)           // 4608 B per warp
#define DD_SMEM_FLOATS (TPB * ROW)          // 36864 B
#define F_SMEM_FLOATS  (TPB * 9)            //  9216 B
#define MAX_BLOCKS (148 * 5)

__device__ __forceinline__ uint32_t smem_u32(const void* p) {
    uint32_t a;
    asm("{ .reg .u64 t; cvta.to.shared.u64 t, %1; cvt.u32.u64 %0, t; }"
        : "=r"(a) : "l"(p));
    return a;
}

// prefetch one warp-tile's F (1152B) into this warp's smem region via LDGSTS
__device__ __forceinline__ void prefetch_F(uint32_t sdst, const float* gsrc, int lane) {
    const char* g = reinterpret_cast<const char*>(gsrc);
    asm volatile("cp.async.cg.shared.global [%0], [%1], 16;"
                 :: "r"(sdst + lane * 16), "l"(g + lane * 16));
    asm volatile("cp.async.cg.shared.global [%0], [%1], 16;"
                 :: "r"(sdst + (lane + 32) * 16), "l"(g + (lane + 32) * 16));
    if (lane < 8)
        asm volatile("cp.async.cg.shared.global [%0], [%1], 16;"
                     :: "r"(sdst + (lane + 64) * 16), "l"(g + (lane + 64) * 16));
    asm volatile("cp.async.commit_group;" ::: "memory");
}

__device__ __forceinline__ void nh3d_point(
    const float F[3][3], float c1, float c2,
    float& psi, float cau[6], float dd[36])
{
    // B = F F^T (symmetric)
    float B[3][3];
    #pragma unroll
    for (int i = 0; i < 3; i++)
        #pragma unroll
        for (int j = 0; j < 3; j++)
            B[i][j] = F[i][0]*F[j][0] + F[i][1]*F[j][1] + F[i][2]*F[j][2];

    float J = F[0][0]*(F[1][1]*F[2][2] - F[1][2]*F[2][1])
            - F[0][1]*(F[1][0]*F[2][2] - F[1][2]*F[2][0])
            + F[0][2]*(F[1][0]*F[2][1] - F[1][1]*F[2][0]);

    float I1   = B[0][0] + B[1][1] + B[2][2];
    float Jm23 = 1.0f / cbrtf(J * J);      // J^{-2/3}
    float invJ = 1.0f / J;

    float a = 2.0f * c1 * Jm23;
    float b = 2.0f * c2 * (J - 1.0f) * J;

    // Kirchhoff stress tau = a*(B - I1/3 * I) + b*I
    float tau[3][3];
    #pragma unroll
    for (int i = 0; i < 3; i++)
        #pragma unroll
        for (int j = 0; j < 3; j++)
            tau[i][j] = a * (B[i][j] - (i == j ? I1 * (1.0f/3.0f) : 0.0f))
                      + (i == j ? b : 0.0f);

    psi = c1 * (Jm23 * I1 - 3.0f) + c2 * (J - 1.0f) * (J - 1.0f);

    // Spatial tangent:
    // Stiff_ijkl = c_dd d_ij d_kl + c_bd (B_ij d_kl + d_ij B_kl)
    //            + a d_ik B_jl + c_sw d_il d_jk
    //            + 0.5*(tau_ik d_jl + tau_il d_jk + tau_jk d_il - tau_jl d_ik)
    float c_dd = (2.0f/9.0f) * a * I1 + 2.0f * c2 * (2.0f*J - 1.0f) * J;
    float c_bd = -(2.0f/3.0f) * a;
    float c_sw = a * I1 * (1.0f/3.0f) - b;

    const int II[6] = {0, 1, 2, 0, 0, 1};
    const int JJ[6] = {0, 1, 2, 1, 2, 2};

    #pragma unroll
    for (int r = 0; r < 6; r++)
        cau[r] = tau[II[r]][JJ[r]] * invJ;

    #pragma unroll
    for (int r = 0; r < 6; r++) {
        const int i = II[r], j = JJ[r];
        #pragma unroll
        for (int c = 0; c < 6; c++) {
            const int k = II[c], l = JJ[c];
            float s = 0.0f;
            if (i == j && k == l) s += c_dd;
            if (k == l)           s += c_bd * B[i][j];
            if (i == j)           s += c_bd * B[k][l];
            if (i == k)           s += a * B[j][l];
            if (i == l && j == k) s += c_sw;
            float g = 0.0f;
            if (j == l) g += tau[i][k];
            if (j == k) g += tau[i][l];
            if (i == l) g += tau[j][k];
            if (i == k) g -= tau[j][l];
            s += 0.5f * g;
            dd[r*6 + c] = s * invJ;
        }
    }
}

__global__ __launch_bounds__(TPB, 5) void nh3d_kernel(
    const float* __restrict__ F_in,
    const float* __restrict__ mat_par,
    float* __restrict__ out,
    int n, int n_tiles, int vec_ok)
{
    __shared__ __align__(16) float sdd[DD_SMEM_FLOATS];
    __shared__ __align__(16) float sf[F_SMEM_FLOATS];

    const int tid  = threadIdx.x;
    const int wid  = tid >> 5;
    const int lane = tid & 31;
    const float c1 = mat_par[0];
    const float c2 = mat_par[1];

    const int gwarp  = blockIdx.x * WARPS_PER_BLOCK + wid;
    const int stride = gridDim.x * WARPS_PER_BLOCK;

    float*   myFbuf   = sf  + wid * WARP_F_FLOATS;
    float*   myDDbuf  = sdd + wid * WARP_DD_FLOATS;
    uint32_t myFbuf_a = smem_u32(myFbuf);
    uint32_t myDD_a   = smem_u32(myDDbuf);

    float F[3][3];
    float psi, cau[6], dd[36];

    // prologue: prefetch first tile's F (fast tiles only)
    int t0 = gwarp;
    if (vec_ok && t0 < n_tiles && (t0 * 32 + 32) <= n)
        prefetch_F(myFbuf_a, F_in + (size_t)t0 * 32 * 9, lane);

    for (int t = gwarp; t < n_tiles; t += stride) {
        const int pt0 = t * 32;

        if (vec_ok && pt0 + 32 <= n) {
            // ---- wait for this tile's F, consume it into registers ----
            asm volatile("cp.async.wait_group 0;" ::: "memory");
            __syncwarp();
            {
                const float* myF = myFbuf + lane * 9;   // stride 9: conflict-free
                #pragma unroll
                for (int i = 0; i < 9; i++)
                    (&F[0][0])[i] = myF[i];
            }
            __syncwarp();   // all lanes consumed F -> buffer reusable

            // ---- prefetch NEXT tile's F; overlaps this tile's compute ----
            {
                int tn = t + stride;
                if (tn < n_tiles && (tn * 32 + 32) <= n)
                    prefetch_F(myFbuf_a, F_in + (size_t)tn * 32 * 9, lane);
            }

            nh3d_point(F, c1, c2, psi, cau, dd);

            // ---- retire PREVIOUS tile's dd TMA before reusing the buffer ----
            if (lane == 0)
                asm volatile("cp.async.bulk.wait_group 0;" ::: "memory");
            __syncwarp();

            // ---- stage dd: lane row 144B, warp chunk 4608B contiguous ----
            {
                float4* row4 = reinterpret_cast<float4*>(myDDbuf + lane * ROW);
                #pragma unroll
                for (int q = 0; q < 9; q++)
                    row4[q] = make_float4(dd[4*q+0], dd[4*q+1], dd[4*q+2], dd[4*q+3]);
            }
            __syncwarp();

            // ---- commit this tile's bulk drain (wait deferred to next iter) ----
            if (lane == 0) {
                asm volatile("fence.proxy.async.shared::cta;" ::: "memory");
                float* ddst = out + (size_t)n * 7 + (size_t)pt0 * 36;
                asm volatile(
                    "cp.async.bulk.global.shared::cta.bulk_group [%0], [%1], %2;"
                    :: "l"(ddst), "r"(myDD_a), "n"(WARP_DD_FLOATS * 4) : "memory");
                asm volatile("cp.async.bulk.commit_group;" ::: "memory");
            }

            // ---- psi + cau direct stores (overlap the TMA) ----
            const int p = pt0 + lane;
            __stcs(out + p, psi);
            {
                float2* c2p = reinterpret_cast<float2*>(out + (size_t)n + (size_t)p * 6);
                __stcs(c2p + 0, make_float2(cau[0], cau[1]));
                __stcs(c2p + 1, make_float2(cau[2], cau[3]));
                __stcs(c2p + 2, make_float2(cau[4], cau[5]));
            }
        } else {
            // ---- tail / unaligned tile: scalar per-lane path ----
            const int p = pt0 + lane;
            if (p < n) {
                const float* Fp = F_in + (size_t)p * 9;
                #pragma unroll
                for (int i = 0; i < 9; i++)
                    (&F[0][0])[i] = __ldcs(Fp + i);

                nh3d_point(F, c1, c2, psi, cau, dd);

                __stcs(out + p, psi);
                float* cbase = out + (size_t)n + (size_t)p * 6;
                #pragma unroll
                for (int q = 0; q < 6; q++) __stcs(cbase + q, cau[q]);
                float* dbase = out + (size_t)n * 7 + (size_t)p * 36;
                #pragma unroll
                for (int q = 0; q < 36; q++) __stcs(dbase + q, dd[q]);
            }
        }
    }

    // epilogue: smem must stay valid until the warp's last TMA completes
    if (lane == 0)
        asm volatile("cp.async.bulk.wait_group 0;" ::: "memory");
}

extern "C" void kernel_launch(void* const* d_in, const int* in_sizes, int n_in,
                              void* d_out, int out_size) {
    const float* F_in    = (const float*)d_in[0];
    const float* mat_par = (const float*)d_in[1];
    float* out = (float*)d_out;
    int n = in_sizes[0] / 9;

    // fast path alignment: dd bulk dst (7n floats + 4608B warp chunks) needs
    // 16B and cau float2 needs 8B -> n % 4 == 0.
    int vec_ok = ((n % 4) == 0) ? 1 : 0;

    int n_tiles = (n + 31) / 32;
    int warps_needed = n_tiles;
    int blocks = (warps_needed + WARPS_PER_BLOCK - 1) / WARPS_PER_BLOCK;
    if (blocks > MAX_BLOCKS) blocks = MAX_BLOCKS;
    nh3d_kernel<<<blocks, TPB>>>(F_in, mat_par, out, n, n_tiles, vec_ok);
}

// round 10
// speedup vs baseline: 1.2783x; 1.2783x over previous
#include <cuda_runtime.h>
#include <cstdint>

// Neo-Hookean 3D material point: psi, Cauchy (Voigt 6), DDSDDE (6x6) per point.
// Output layout (flattened tuple): [N] psi | [N,6] Cauchy6 | [N,36] DDSDDE.
//
// R9: one-shot warp-local blocks (persistent loops regressed twice), but
// TPB=128 so smem/block = 23KB -> 9 blocks/SM instead of 5. Same total warps
// per SM, but 9 independently scheduled TMA-wait tails instead of 5, finer
// stagger, less dead slot time. psi/cau stores issue right after compute.

#define TPB 128
#define ROW 36
#define WARPS_PER_BLOCK (TPB / 32)
#define WARP_F_FLOATS  (32 * 9)             // 1152 B per warp
#define WARP_DD_FLOATS (32 * ROW)           // 4608 B per warp
#define DD_SMEM_FLOATS (TPB * ROW)          // 18432 B
#define F_SMEM_FLOATS  (TPB * 9)            //  4608 B

__device__ __forceinline__ uint32_t smem_u32(const void* p) {
    uint32_t a;
    asm("{ .reg .u64 t; cvta.to.shared.u64 t, %1; cvt.u32.u64 %0, t; }"
        : "=r"(a) : "l"(p));
    return a;
}

__device__ __forceinline__ void nh3d_point(
    const float F[3][3], float c1, float c2,
    float& psi, float cau[6], float dd[36])
{
    // B = F F^T (symmetric)
    float B[3][3];
    #pragma unroll
    for (int i = 0; i < 3; i++)
        #pragma unroll
        for (int j = 0; j < 3; j++)
            B[i][j] = F[i][0]*F[j][0] + F[i][1]*F[j][1] + F[i][2]*F[j][2];

    float J = F[0][0]*(F[1][1]*F[2][2] - F[1][2]*F[2][1])
            - F[0][1]*(F[1][0]*F[2][2] - F[1][2]*F[2][0])
            + F[0][2]*(F[1][0]*F[2][1] - F[1][1]*F[2][0]);

    float I1   = B[0][0] + B[1][1] + B[2][2];
    float Jm23 = 1.0f / cbrtf(J * J);      // J^{-2/3}
    float invJ = 1.0f / J;

    float a = 2.0f * c1 * Jm23;
    float b = 2.0f * c2 * (J - 1.0f) * J;

    // Kirchhoff stress tau = a*(B - I1/3 * I) + b*I
    float tau[3][3];
    #pragma unroll
    for (int i = 0; i < 3; i++)
        #pragma unroll
        for (int j = 0; j < 3; j++)
            tau[i][j] = a * (B[i][j] - (i == j ? I1 * (1.0f/3.0f) : 0.0f))
                      + (i == j ? b : 0.0f);

    psi = c1 * (Jm23 * I1 - 3.0f) + c2 * (J - 1.0f) * (J - 1.0f);

    // Spatial tangent:
    // Stiff_ijkl = c_dd d_ij d_kl + c_bd (B_ij d_kl + d_ij B_kl)
    //            + a d_ik B_jl + c_sw d_il d_jk
    //            + 0.5*(tau_ik d_jl + tau_il d_jk + tau_jk d_il - tau_jl d_ik)
    float c_dd = (2.0f/9.0f) * a * I1 + 2.0f * c2 * (2.0f*J - 1.0f) * J;
    float c_bd = -(2.0f/3.0f) * a;
    float c_sw = a * I1 * (1.0f/3.0f) - b;

    const int II[6] = {0, 1, 2, 0, 0, 1};
    const int JJ[6] = {0, 1, 2, 1, 2, 2};

    #pragma unroll
    for (int r = 0; r < 6; r++)
        cau[r] = tau[II[r]][JJ[r]] * invJ;

    #pragma unroll
    for (int r = 0; r < 6; r++) {
        const int i = II[r], j = JJ[r];
        #pragma unroll
        for (int c = 0; c < 6; c++) {
            const int k = II[c], l = JJ[c];
            float s = 0.0f;
            if (i == j && k == l) s += c_dd;
            if (k == l)           s += c_bd * B[i][j];
            if (i == j)           s += c_bd * B[k][l];
            if (i == k)           s += a * B[j][l];
            if (i == l && j == k) s += c_sw;
            float g = 0.0f;
            if (j == l) g += tau[i][k];
            if (j == k) g += tau[i][l];
            if (i == l) g += tau[j][k];
            if (i == k) g -= tau[j][l];
            s += 0.5f * g;
            dd[r*6 + c] = s * invJ;
        }
    }
}

__global__ __launch_bounds__(TPB, 9) void nh3d_kernel(
    const float* __restrict__ F_in,
    const float* __restrict__ mat_par,
    float* __restrict__ out,
    int n, int vec_ok)
{
    __shared__ __align__(16) float sdd[DD_SMEM_FLOATS];  // 18432 B
    __shared__ __align__(16) float sf[F_SMEM_FLOATS];    //  4608 B

    const int tid  = threadIdx.x;
    const int wid  = tid >> 5;
    const int lane = tid & 31;
    const int block_start = blockIdx.x * TPB;
    const float c1 = mat_par[0];
    const float c2 = mat_par[1];

    float F[3][3];
    float psi, cau[6], dd[36];

    if (vec_ok && block_start + TPB <= n) {
        const int warp_pt0 = block_start + wid * 32;   // first point of this warp

        // ---- warp-local F staging: 72 float4 (1152B contiguous) per warp ----
        {
            const float4* g4 = reinterpret_cast<const float4*>(F_in + (size_t)warp_pt0 * 9);
            float4* s4 = reinterpret_cast<float4*>(sf + wid * WARP_F_FLOATS);
            s4[lane]      = __ldcs(g4 + lane);
            s4[lane + 32] = __ldcs(g4 + lane + 32);
            if (lane < 8) s4[lane + 64] = __ldcs(g4 + lane + 64);
        }
        __syncwarp();
        {
            const float* myF = sf + wid * WARP_F_FLOATS + lane * 9;  // stride 9: conflict-free
            #pragma unroll
            for (int i = 0; i < 9; i++)
                (&F[0][0])[i] = myF[i];
        }

        nh3d_point(F, c1, c2, psi, cau, dd);

        // ---- psi + cau direct stores first: start the write stream early ----
        {
            const int p = warp_pt0 + lane;
            __stcs(out + p, psi);
            float2* c2p = reinterpret_cast<float2*>(out + (size_t)n + (size_t)p * 6);
            __stcs(c2p + 0, make_float2(cau[0], cau[1]));
            __stcs(c2p + 1, make_float2(cau[2], cau[3]));
            __stcs(c2p + 2, make_float2(cau[4], cau[5]));
        }

        // ---- warp-local dd staging: lane row 144B, warp chunk 4608B ----
        {
            float4* row4 = reinterpret_cast<float4*>(sdd + wid * WARP_DD_FLOATS + lane * ROW);
            #pragma unroll
            for (int q = 0; q < 9; q++)
                row4[q] = make_float4(dd[4*q+0], dd[4*q+1], dd[4*q+2], dd[4*q+3]);
        }
        __syncwarp();

        // lane 0 drains this warp's contiguous chunk with one bulk copy
        if (lane == 0) {
            asm volatile("fence.proxy.async.shared::cta;" ::: "memory");
            float* ddst = out + (size_t)n * 7 + (size_t)warp_pt0 * 36;
            uint32_t src = smem_u32(sdd + wid * WARP_DD_FLOATS);
            asm volatile(
                "cp.async.bulk.global.shared::cta.bulk_group [%0], [%1], %2;"
                :: "l"(ddst), "r"(src), "n"(WARP_DD_FLOATS * 4) : "memory");
            asm volatile("cp.async.bulk.commit_group;" ::: "memory");
            // retire before block exit (smem must stay valid)
            asm volatile("cp.async.bulk.wait_group 0;" ::: "memory");
        }
    } else {
        // ---- tail / unaligned fallback: scalar path ----
        const int p = block_start + tid;
        if (p >= n) return;
        const float* Fp = F_in + (size_t)p * 9;
        #pragma unroll
        for (int i = 0; i < 9; i++)
            (&F[0][0])[i] = __ldcs(Fp + i);

        nh3d_point(F, c1, c2, psi, cau, dd);

        __stcs(out + p, psi);
        float* cbase = out + (size_t)n + (size_t)p * 6;
        #pragma unroll
        for (int q = 0; q < 6; q++) __stcs(cbase + q, cau[q]);
        float* dbase = out + (size_t)n * 7 + (size_t)p * 36;
        #pragma unroll
        for (int q = 0; q < 36; q++) __stcs(dbase + q, dd[q]);
    }
}

extern "C" void kernel_launch(void* const* d_in, const int* in_sizes, int n_in,
                              void* d_out, int out_size) {
    const float* F_in    = (const float*)d_in[0];
    const float* mat_par = (const float*)d_in[1];
    float* out = (float*)d_out;
    int n = in_sizes[0] / 9;

    // fast path: dd bulk dst (7n floats, 4608B warp chunks) needs 16B,
    // cau float2 needs 8B -> n % 4 == 0.
    int vec_ok = ((n % 4) == 0) ? 1 : 0;

    int blocks = (n + TPB - 1) / TPB;
    nh3d_kernel<<<blocks, TPB>>>(F_in, mat_par, out, n, vec_ok);
}